// round 2
// baseline (speedup 1.0000x reference)
#include <cuda_runtime.h>

// DMaSIFConvBlock: out = relu(f @ (Wa·Wt)^T + (Wa·bt+ba)) @ Wb^T + bb
// N = 2e6 points, C=16. Memory-bound: 256 MB traffic.

__device__ __forceinline__ float2 ffma2(float2 a, float2 b, float2 c) {
    float2 d;
    asm("{\n\t"
        ".reg .b64 ra, rb, rc, rd;\n\t"
        "mov.b64 ra, {%2,%3};\n\t"
        "mov.b64 rb, {%4,%5};\n\t"
        "mov.b64 rc, {%6,%7};\n\t"
        "fma.rn.f32x2 rd, ra, rb, rc;\n\t"
        "mov.b64 {%0,%1}, rd;\n\t"
        "}"
        : "=f"(d.x), "=f"(d.y)
        : "f"(a.x), "f"(a.y), "f"(b.x), "f"(b.y), "f"(c.x), "f"(c.y));
    return d;
}

__global__ void __launch_bounds__(256, 4)
dmasif_fused_kernel(const float4* __restrict__ feat4,
                    const float* __restrict__ Wt,
                    const float* __restrict__ bt,
                    const float* __restrict__ Wa,
                    const float* __restrict__ ba,
                    const float* __restrict__ Wb,
                    const float* __restrict__ bb,
                    float4* __restrict__ out4,
                    int n)
{
    // Packed weights: sW1[j][p] = (W1[2p][j], W1[2p+1][j]) where W1 = Wa @ Wt.
    __shared__ float2 sW1[16][8];
    __shared__ float2 sWb[16][8];
    __shared__ float2 sb1[8];
    __shared__ float2 sbb[8];

    const int t = threadIdx.x;
    if (t < 128) {
        const int j = t >> 3;      // input channel 0..15
        const int p = t & 7;       // output pair 0..7
        float x = 0.f, y = 0.f;
        #pragma unroll
        for (int k = 0; k < 16; k++) {
            const float wt = Wt[k * 16 + j];       // Wt[k][j]
            x = fmaf(Wa[(2 * p) * 16 + k], wt, x);     // sum_k Wa[2p][k]  Wt[k][j]
            y = fmaf(Wa[(2 * p + 1) * 16 + k], wt, y); // sum_k Wa[2p+1][k] Wt[k][j]
        }
        sW1[j][p] = make_float2(x, y);
        sWb[j][p] = make_float2(Wb[(2 * p) * 16 + j], Wb[(2 * p + 1) * 16 + j]);
        if (j == 0) {
            float bx = ba[2 * p], by = ba[2 * p + 1];
            #pragma unroll
            for (int k = 0; k < 16; k++) {
                const float btk = bt[k];
                bx = fmaf(Wa[(2 * p) * 16 + k], btk, bx);
                by = fmaf(Wa[(2 * p + 1) * 16 + k], btk, by);
            }
            sb1[p] = make_float2(bx, by);
            sbb[p] = make_float2(bb[2 * p], bb[2 * p + 1]);
        }
    }
    __syncthreads();

    const int i = blockIdx.x * blockDim.x + threadIdx.x;
    if (i >= n) return;

    // Load 16 features (64B contiguous per point).
    const float4 f0 = feat4[i * 4 + 0];
    const float4 f1 = feat4[i * 4 + 1];
    const float4 f2 = feat4[i * 4 + 2];
    const float4 f3 = feat4[i * 4 + 3];
    float f[16] = {f0.x, f0.y, f0.z, f0.w,
                   f1.x, f1.y, f1.z, f1.w,
                   f2.x, f2.y, f2.z, f2.w,
                   f3.x, f3.y, f3.z, f3.w};

    // Layer 1 (fused Wt+Wa): h = f @ W1^T + b1, packed 2 channels per float2.
    float2 acc[8];
    #pragma unroll
    for (int p = 0; p < 8; p++) acc[p] = sb1[p];
    #pragma unroll
    for (int j = 0; j < 16; j++) {
        const float2 ff = make_float2(f[j], f[j]);
        #pragma unroll
        for (int p = 0; p < 8; p++) acc[p] = ffma2(ff, sW1[j][p], acc[p]);
    }

    // ReLU
    #pragma unroll
    for (int p = 0; p < 8; p++) {
        acc[p].x = fmaxf(acc[p].x, 0.f);
        acc[p].y = fmaxf(acc[p].y, 0.f);
    }

    // Layer 2: out = h @ Wb^T + bb
    float2 acc2[8];
    #pragma unroll
    for (int p = 0; p < 8; p++) acc2[p] = sbb[p];
    #pragma unroll
    for (int j = 0; j < 16; j++) {
        const float hj = (j & 1) ? acc[j >> 1].y : acc[j >> 1].x;
        const float2 ff = make_float2(hj, hj);
        #pragma unroll
        for (int p = 0; p < 8; p++) acc2[p] = ffma2(ff, sWb[j][p], acc2[p]);
    }

    out4[i * 4 + 0] = make_float4(acc2[0].x, acc2[0].y, acc2[1].x, acc2[1].y);
    out4[i * 4 + 1] = make_float4(acc2[2].x, acc2[2].y, acc2[3].x, acc2[3].y);
    out4[i * 4 + 2] = make_float4(acc2[4].x, acc2[4].y, acc2[5].x, acc2[5].y);
    out4[i * 4 + 3] = make_float4(acc2[6].x, acc2[6].y, acc2[7].x, acc2[7].y);
}

extern "C" void kernel_launch(void* const* d_in, const int* in_sizes, int n_in,
                              void* d_out, int out_size)
{
    // metadata order: features, points, nuv, Wt, bt, Wa, ba, Wb, bb, ranges
    const float4* feat = (const float4*)d_in[0];
    const float*  Wt   = (const float*)d_in[3];
    const float*  bt   = (const float*)d_in[4];
    const float*  Wa   = (const float*)d_in[5];
    const float*  ba   = (const float*)d_in[6];
    const float*  Wb   = (const float*)d_in[7];
    const float*  bb   = (const float*)d_in[8];
    float4* out = (float4*)d_out;

    const int n = in_sizes[0] / 16;   // number of points
    const int threads = 256;
    const int blocks = (n + threads - 1) / threads;
    dmasif_fused_kernel<<<blocks, threads>>>(feat, Wt, bt, Wa, ba, Wb, bb, out, n);
}

// round 3
// speedup vs baseline: 1.4082x; 1.4082x over previous
#include <cuda_runtime.h>

typedef unsigned long long ull;

// Packed f32x2 FMA: d = a*b+c on both lanes. Only reachable via PTX.
__device__ __forceinline__ ull ffma2(ull a, ull b, ull c) {
    ull d;
    asm("fma.rn.f32x2 %0, %1, %2, %3;" : "=l"(d) : "l"(a), "l"(b), "l"(c));
    return d;
}
__device__ __forceinline__ ull bcast2(float x) {
    ull r;
    asm("mov.b64 %0, {%1, %1};" : "=l"(r) : "f"(x));
    return r;
}
__device__ __forceinline__ ull pack2(float x, float y) {
    ull r;
    asm("mov.b64 %0, {%1, %2};" : "=l"(r) : "f"(x), "f"(y));
    return r;
}
__device__ __forceinline__ float2 unpack2(ull v) {
    float2 r;
    asm("mov.b64 {%0, %1}, %2;" : "=f"(r.x), "=f"(r.y) : "l"(v));
    return r;
}

// out = relu(f @ W1^T + b1) @ Wb^T + bb,  W1 = Wa@Wt, b1 = Wa@bt + ba.
// 2 points per thread (block-stride 256). Weights pre-packed as u64 pairs in smem.
__global__ void __launch_bounds__(256)
dmasif_fused_kernel(const float4* __restrict__ feat4,
                    const float* __restrict__ Wt,
                    const float* __restrict__ bt,
                    const float* __restrict__ Wa,
                    const float* __restrict__ ba,
                    const float* __restrict__ Wb,
                    const float* __restrict__ bb,
                    float4* __restrict__ out4,
                    int n)
{
    // sW1u[j][p] holds packed (W1[2p][j], W1[2p+1][j]); row = 64B, 16B-aligned.
    __shared__ __align__(16) ull sW1u[16][8];
    __shared__ __align__(16) ull sWbu[16][8];
    __shared__ ull sb1u[8];
    __shared__ ull sbbu[8];

    const int t = threadIdx.x;
    if (t < 128) {
        const int j = t >> 3;   // input channel 0..15
        const int p = t & 7;    // output pair 0..7
        float x = 0.f, y = 0.f;
        #pragma unroll
        for (int k = 0; k < 16; k++) {
            const float wt = Wt[k * 16 + j];           // Wt[k][j]
            x = fmaf(Wa[(2 * p) * 16 + k], wt, x);     // (Wa@Wt)[2p][j]
            y = fmaf(Wa[(2 * p + 1) * 16 + k], wt, y); // (Wa@Wt)[2p+1][j]
        }
        sW1u[j][p] = pack2(x, y);
        sWbu[j][p] = pack2(Wb[(2 * p) * 16 + j], Wb[(2 * p + 1) * 16 + j]);
        if (j == 0) {
            float bx = ba[2 * p], by = ba[2 * p + 1];
            #pragma unroll
            for (int k = 0; k < 16; k++) {
                const float btk = bt[k];
                bx = fmaf(Wa[(2 * p) * 16 + k], btk, bx);
                by = fmaf(Wa[(2 * p + 1) * 16 + k], btk, by);
            }
            sb1u[p] = pack2(bx, by);
            sbbu[p] = pack2(bb[2 * p], bb[2 * p + 1]);
        }
    }
    __syncthreads();

    const int i0 = blockIdx.x * 512 + t;
    const int i1 = i0 + 256;
    const bool v0 = i0 < n;
    const bool v1 = i1 < n;

    // Load features for both points (LDG.128 x8, front-batched for MLP).
    float f0[16], f1[16];
    {
        float4 a0 = {}, a1 = {}, a2 = {}, a3 = {};
        float4 c0 = {}, c1 = {}, c2 = {}, c3 = {};
        if (v0) {
            a0 = feat4[i0 * 4 + 0]; a1 = feat4[i0 * 4 + 1];
            a2 = feat4[i0 * 4 + 2]; a3 = feat4[i0 * 4 + 3];
        }
        if (v1) {
            c0 = feat4[i1 * 4 + 0]; c1 = feat4[i1 * 4 + 1];
            c2 = feat4[i1 * 4 + 2]; c3 = feat4[i1 * 4 + 3];
        }
        f0[0]=a0.x; f0[1]=a0.y; f0[2]=a0.z; f0[3]=a0.w;
        f0[4]=a1.x; f0[5]=a1.y; f0[6]=a1.z; f0[7]=a1.w;
        f0[8]=a2.x; f0[9]=a2.y; f0[10]=a2.z; f0[11]=a2.w;
        f0[12]=a3.x; f0[13]=a3.y; f0[14]=a3.z; f0[15]=a3.w;
        f1[0]=c0.x; f1[1]=c0.y; f1[2]=c0.z; f1[3]=c0.w;
        f1[4]=c1.x; f1[5]=c1.y; f1[6]=c1.z; f1[7]=c1.w;
        f1[8]=c2.x; f1[9]=c2.y; f1[10]=c2.z; f1[11]=c2.w;
        f1[12]=c3.x; f1[13]=c3.y; f1[14]=c3.z; f1[15]=c3.w;
    }

    // ---------------- Layer 1 (fused Wt+Wa), both points share weight loads ----
    ull acc0[8], acc1[8];
    #pragma unroll
    for (int p = 0; p < 8; p++) { acc0[p] = sb1u[p]; acc1[p] = sb1u[p]; }

    #pragma unroll
    for (int j = 0; j < 16; j++) {
        const ulonglong2* wrow = reinterpret_cast<const ulonglong2*>(sW1u[j]);
        const ull ff0 = bcast2(f0[j]);
        const ull ff1 = bcast2(f1[j]);
        #pragma unroll
        for (int q = 0; q < 4; q++) {
            const ulonglong2 w = wrow[q];          // LDS.128: pairs 2q, 2q+1
            acc0[2*q+0] = ffma2(ff0, w.x, acc0[2*q+0]);
            acc0[2*q+1] = ffma2(ff0, w.y, acc0[2*q+1]);
            acc1[2*q+0] = ffma2(ff1, w.x, acc1[2*q+0]);
            acc1[2*q+1] = ffma2(ff1, w.y, acc1[2*q+1]);
        }
    }

    // ReLU -> scalar h (reuses f register space; f is dead now).
    float h0[16], h1[16];
    #pragma unroll
    for (int p = 0; p < 8; p++) {
        float2 u0 = unpack2(acc0[p]);
        float2 u1 = unpack2(acc1[p]);
        h0[2*p+0] = fmaxf(u0.x, 0.f); h0[2*p+1] = fmaxf(u0.y, 0.f);
        h1[2*p+0] = fmaxf(u1.x, 0.f); h1[2*p+1] = fmaxf(u1.y, 0.f);
    }

    // ---------------- Layer 2 ----------------
    #pragma unroll
    for (int p = 0; p < 8; p++) { acc0[p] = sbbu[p]; acc1[p] = sbbu[p]; }

    #pragma unroll
    for (int j = 0; j < 16; j++) {
        const ulonglong2* wrow = reinterpret_cast<const ulonglong2*>(sWbu[j]);
        const ull ff0 = bcast2(h0[j]);
        const ull ff1 = bcast2(h1[j]);
        #pragma unroll
        for (int q = 0; q < 4; q++) {
            const ulonglong2 w = wrow[q];
            acc0[2*q+0] = ffma2(ff0, w.x, acc0[2*q+0]);
            acc0[2*q+1] = ffma2(ff0, w.y, acc0[2*q+1]);
            acc1[2*q+0] = ffma2(ff1, w.x, acc1[2*q+0]);
            acc1[2*q+1] = ffma2(ff1, w.y, acc1[2*q+1]);
        }
    }

    // Store (STG.128 x8, predicated).
    if (v0) {
        #pragma unroll
        for (int q = 0; q < 4; q++) {
            float2 lo = unpack2(acc0[2*q+0]);
            float2 hi = unpack2(acc0[2*q+1]);
            out4[i0 * 4 + q] = make_float4(lo.x, lo.y, hi.x, hi.y);
        }
    }
    if (v1) {
        #pragma unroll
        for (int q = 0; q < 4; q++) {
            float2 lo = unpack2(acc1[2*q+0]);
            float2 hi = unpack2(acc1[2*q+1]);
            out4[i1 * 4 + q] = make_float4(lo.x, lo.y, hi.x, hi.y);
        }
    }
}

extern "C" void kernel_launch(void* const* d_in, const int* in_sizes, int n_in,
                              void* d_out, int out_size)
{
    // metadata order: features, points, nuv, Wt, bt, Wa, ba, Wb, bb, ranges
    const float4* feat = (const float4*)d_in[0];
    const float*  Wt   = (const float*)d_in[3];
    const float*  bt   = (const float*)d_in[4];
    const float*  Wa   = (const float*)d_in[5];
    const float*  ba   = (const float*)d_in[6];
    const float*  Wb   = (const float*)d_in[7];
    const float*  bb   = (const float*)d_in[8];
    float4* out = (float4*)d_out;

    const int n = in_sizes[0] / 16;               // number of points
    const int blocks = (n + 511) / 512;           // 2 points per thread
    dmasif_fused_kernel<<<blocks, 256>>>(feat, Wt, bt, Wa, ba, Wb, bb, out, n);
}

// round 4
// speedup vs baseline: 1.5971x; 1.1342x over previous
#include <cuda_runtime.h>

typedef unsigned long long ull;

__device__ __forceinline__ ull ffma2(ull a, ull b, ull c) {
    ull d;
    asm("fma.rn.f32x2 %0, %1, %2, %3;" : "=l"(d) : "l"(a), "l"(b), "l"(c));
    return d;
}
__device__ __forceinline__ ull bcast2(float x) {
    ull r; asm("mov.b64 %0, {%1, %1};" : "=l"(r) : "f"(x)); return r;
}
__device__ __forceinline__ ull pack2(float x, float y) {
    ull r; asm("mov.b64 %0, {%1, %2};" : "=l"(r) : "f"(x), "f"(y)); return r;
}
__device__ __forceinline__ float2 unpack2(ull v) {
    float2 r; asm("mov.b64 {%0, %1}, %2;" : "=f"(r.x), "=f"(r.y) : "l"(v)); return r;
}

// out = relu(f @ W1^T + b1) @ Wb^T + bb,  W1 = Wa@Wt, b1 = Wa@bt + ba.
// 4 lanes cooperate per point; each lane owns 4 output channels.
// All weights live in registers (permuted per-lane gather order); features and
// the intermediate h are exchanged with SHFL.IDX inside the 4-lane group.
__global__ void __launch_bounds__(128)
dmasif_shfl_kernel(const float4* __restrict__ feat4,
                   const float* __restrict__ Wt,
                   const float* __restrict__ bt,
                   const float* __restrict__ Wa,
                   const float* __restrict__ ba,
                   const float* __restrict__ Wb,
                   const float* __restrict__ bb,
                   float4* __restrict__ out4,
                   int n)
{
    __shared__ float sW1[16][16];   // fused Wa@Wt, [out][in]
    __shared__ float sWb[16][16];   // Wb, [out][in]
    __shared__ float sb1[16];
    __shared__ float sbb[16];

    const int t = threadIdx.x;
    // ---- one-time weight fusion (cheap, every block) ----
    #pragma unroll
    for (int e = t; e < 256; e += 128) {
        const int c = e >> 4, j = e & 15;
        float acc = 0.f;
        #pragma unroll
        for (int k = 0; k < 16; k++)
            acc = fmaf(Wa[c * 16 + k], Wt[k * 16 + j], acc);
        sW1[c][j] = acc;
        sWb[c][j] = Wb[c * 16 + j];
    }
    if (t < 16) {
        float acc = ba[t];
        #pragma unroll
        for (int k = 0; k < 16; k++)
            acc = fmaf(Wa[t * 16 + k], bt[k], acc);
        sb1[t] = acc;
        sbb[t] = bb[t];
    }
    __syncthreads();

    const int lane = t & 31;
    const int q = lane & 3;           // quarter within the 4-lane point group

    // ---- load register-resident weights, permuted to this lane's gather order ----
    // input index visited at step i is channel j = ((q + i/4)&3)*4 + i%4
    ull w1a[16], w1b[16], wba[16], wbb[16];
    #pragma unroll
    for (int i = 0; i < 16; i++) {
        const int j = (((q + (i >> 2)) & 3) << 2) | (i & 3);
        w1a[i] = pack2(sW1[4 * q + 0][j], sW1[4 * q + 1][j]);
        w1b[i] = pack2(sW1[4 * q + 2][j], sW1[4 * q + 3][j]);
        wba[i] = pack2(sWb[4 * q + 0][j], sWb[4 * q + 1][j]);
        wbb[i] = pack2(sWb[4 * q + 2][j], sWb[4 * q + 3][j]);
    }
    const ull b1p0 = pack2(sb1[4 * q + 0], sb1[4 * q + 1]);
    const ull b1p1 = pack2(sb1[4 * q + 2], sb1[4 * q + 3]);
    const ull bbp0 = pack2(sbb[4 * q + 0], sbb[4 * q + 1]);
    const ull bbp1 = pack2(sbb[4 * q + 2], sbb[4 * q + 3]);

    const unsigned FULL = 0xffffffffu;
    const int sb = lane & ~3;
    const int s1 = sb | ((q + 1) & 3);
    const int s2 = sb | ((q + 2) & 3);
    const int s3 = sb | ((q + 3) & 3);

    const int gwarp   = (blockIdx.x * blockDim.x + t) >> 5;
    const int nwarps  = (gridDim.x * blockDim.x) >> 5;
    const int ngroups = (n + 7) >> 3;      // 8 points per warp-iter
    if (gwarp >= ngroups) return;

    int grp = gwarp;
    float4 fcur;
    {
        const int p = grp * 8 + (lane >> 2);
        fcur = (p < n) ? feat4[grp * 32 + lane] : make_float4(0.f, 0.f, 0.f, 0.f);
    }

    for (;;) {
        const int nxt = grp + nwarps;
        const bool has_next = nxt < ngroups;
        float4 fnext = make_float4(0.f, 0.f, 0.f, 0.f);
        if (has_next) {
            const int pn = nxt * 8 + (lane >> 2);
            if (pn < n) fnext = feat4[nxt * 32 + lane];
        }

        // -------- layer 1 --------
        ull a0 = b1p0, a1 = b1p1;
        a0 = ffma2(bcast2(fcur.x), w1a[0], a0);  a1 = ffma2(bcast2(fcur.x), w1b[0], a1);
        a0 = ffma2(bcast2(fcur.y), w1a[1], a0);  a1 = ffma2(bcast2(fcur.y), w1b[1], a1);
        a0 = ffma2(bcast2(fcur.z), w1a[2], a0);  a1 = ffma2(bcast2(fcur.z), w1b[2], a1);
        a0 = ffma2(bcast2(fcur.w), w1a[3], a0);  a1 = ffma2(bcast2(fcur.w), w1b[3], a1);
        {
            const float gx = __shfl_sync(FULL, fcur.x, s1), gy = __shfl_sync(FULL, fcur.y, s1);
            const float gz = __shfl_sync(FULL, fcur.z, s1), gw = __shfl_sync(FULL, fcur.w, s1);
            a0 = ffma2(bcast2(gx), w1a[4], a0);  a1 = ffma2(bcast2(gx), w1b[4], a1);
            a0 = ffma2(bcast2(gy), w1a[5], a0);  a1 = ffma2(bcast2(gy), w1b[5], a1);
            a0 = ffma2(bcast2(gz), w1a[6], a0);  a1 = ffma2(bcast2(gz), w1b[6], a1);
            a0 = ffma2(bcast2(gw), w1a[7], a0);  a1 = ffma2(bcast2(gw), w1b[7], a1);
        }
        {
            const float gx = __shfl_sync(FULL, fcur.x, s2), gy = __shfl_sync(FULL, fcur.y, s2);
            const float gz = __shfl_sync(FULL, fcur.z, s2), gw = __shfl_sync(FULL, fcur.w, s2);
            a0 = ffma2(bcast2(gx), w1a[8], a0);   a1 = ffma2(bcast2(gx), w1b[8], a1);
            a0 = ffma2(bcast2(gy), w1a[9], a0);   a1 = ffma2(bcast2(gy), w1b[9], a1);
            a0 = ffma2(bcast2(gz), w1a[10], a0);  a1 = ffma2(bcast2(gz), w1b[10], a1);
            a0 = ffma2(bcast2(gw), w1a[11], a0);  a1 = ffma2(bcast2(gw), w1b[11], a1);
        }
        {
            const float gx = __shfl_sync(FULL, fcur.x, s3), gy = __shfl_sync(FULL, fcur.y, s3);
            const float gz = __shfl_sync(FULL, fcur.z, s3), gw = __shfl_sync(FULL, fcur.w, s3);
            a0 = ffma2(bcast2(gx), w1a[12], a0);  a1 = ffma2(bcast2(gx), w1b[12], a1);
            a0 = ffma2(bcast2(gy), w1a[13], a0);  a1 = ffma2(bcast2(gy), w1b[13], a1);
            a0 = ffma2(bcast2(gz), w1a[14], a0);  a1 = ffma2(bcast2(gz), w1b[14], a1);
            a0 = ffma2(bcast2(gw), w1a[15], a0);  a1 = ffma2(bcast2(gw), w1b[15], a1);
        }

        // -------- ReLU (this lane owns h channels 4q..4q+3) --------
        const float2 u0 = unpack2(a0), u1 = unpack2(a1);
        const float h0 = fmaxf(u0.x, 0.f), h1 = fmaxf(u0.y, 0.f);
        const float h2 = fmaxf(u1.x, 0.f), h3 = fmaxf(u1.y, 0.f);

        // -------- layer 2 --------
        a0 = bbp0; a1 = bbp1;
        a0 = ffma2(bcast2(h0), wba[0], a0);  a1 = ffma2(bcast2(h0), wbb[0], a1);
        a0 = ffma2(bcast2(h1), wba[1], a0);  a1 = ffma2(bcast2(h1), wbb[1], a1);
        a0 = ffma2(bcast2(h2), wba[2], a0);  a1 = ffma2(bcast2(h2), wbb[2], a1);
        a0 = ffma2(bcast2(h3), wba[3], a0);  a1 = ffma2(bcast2(h3), wbb[3], a1);
        {
            const float gx = __shfl_sync(FULL, h0, s1), gy = __shfl_sync(FULL, h1, s1);
            const float gz = __shfl_sync(FULL, h2, s1), gw = __shfl_sync(FULL, h3, s1);
            a0 = ffma2(bcast2(gx), wba[4], a0);  a1 = ffma2(bcast2(gx), wbb[4], a1);
            a0 = ffma2(bcast2(gy), wba[5], a0);  a1 = ffma2(bcast2(gy), wbb[5], a1);
            a0 = ffma2(bcast2(gz), wba[6], a0);  a1 = ffma2(bcast2(gz), wbb[6], a1);
            a0 = ffma2(bcast2(gw), wba[7], a0);  a1 = ffma2(bcast2(gw), wbb[7], a1);
        }
        {
            const float gx = __shfl_sync(FULL, h0, s2), gy = __shfl_sync(FULL, h1, s2);
            const float gz = __shfl_sync(FULL, h2, s2), gw = __shfl_sync(FULL, h3, s2);
            a0 = ffma2(bcast2(gx), wba[8], a0);   a1 = ffma2(bcast2(gx), wbb[8], a1);
            a0 = ffma2(bcast2(gy), wba[9], a0);   a1 = ffma2(bcast2(gy), wbb[9], a1);
            a0 = ffma2(bcast2(gz), wba[10], a0);  a1 = ffma2(bcast2(gz), wbb[10], a1);
            a0 = ffma2(bcast2(gw), wba[11], a0);  a1 = ffma2(bcast2(gw), wbb[11], a1);
        }
        {
            const float gx = __shfl_sync(FULL, h0, s3), gy = __shfl_sync(FULL, h1, s3);
            const float gz = __shfl_sync(FULL, h2, s3), gw = __shfl_sync(FULL, h3, s3);
            a0 = ffma2(bcast2(gx), wba[12], a0);  a1 = ffma2(bcast2(gx), wbb[12], a1);
            a0 = ffma2(bcast2(gy), wba[13], a0);  a1 = ffma2(bcast2(gy), wbb[13], a1);
            a0 = ffma2(bcast2(gz), wba[14], a0);  a1 = ffma2(bcast2(gz), wbb[14], a1);
            a0 = ffma2(bcast2(gw), wba[15], a0);  a1 = ffma2(bcast2(gw), wbb[15], a1);
        }

        // -------- store (this lane's 4 channels are a contiguous float4) --------
        {
            const int p = grp * 8 + (lane >> 2);
            if (p < n) {
                const float2 r0 = unpack2(a0), r1 = unpack2(a1);
                out4[grp * 32 + lane] = make_float4(r0.x, r0.y, r1.x, r1.y);
            }
        }

        if (!has_next) break;
        grp = nxt;
        fcur = fnext;
    }
}

extern "C" void kernel_launch(void* const* d_in, const int* in_sizes, int n_in,
                              void* d_out, int out_size)
{
    // metadata order: features, points, nuv, Wt, bt, Wa, ba, Wb, bb, ranges
    const float4* feat = (const float4*)d_in[0];
    const float*  Wt   = (const float*)d_in[3];
    const float*  bt   = (const float*)d_in[4];
    const float*  Wa   = (const float*)d_in[5];
    const float*  ba   = (const float*)d_in[6];
    const float*  Wb   = (const float*)d_in[7];
    const float*  bb   = (const float*)d_in[8];
    float4* out = (float4*)d_out;

    const int n = in_sizes[0] / 16;   // number of points
    const int ngroups = (n + 7) / 8;
    int blocks = 148 * 8;             // grid-stride; plenty of warps per SM
    const int maxBlocks = (ngroups * 32 + 127) / 128;
    if (blocks > maxBlocks) blocks = maxBlocks;
    if (blocks < 1) blocks = 1;
    dmasif_shfl_kernel<<<blocks, 128>>>(feat, Wt, bt, Wa, ba, Wb, bb, out, n);
}

// round 5
// speedup vs baseline: 1.6047x; 1.0047x over previous
#include <cuda_runtime.h>

typedef unsigned long long ull;

__device__ __forceinline__ ull ffma2(ull a, ull b, ull c) {
    ull d;
    asm("fma.rn.f32x2 %0, %1, %2, %3;" : "=l"(d) : "l"(a), "l"(b), "l"(c));
    return d;
}
__device__ __forceinline__ ull add2(ull a, ull b) {
    ull d;
    asm("add.rn.f32x2 %0, %1, %2;" : "=l"(d) : "l"(a), "l"(b));
    return d;
}
__device__ __forceinline__ ull bcast2(float x) {
    ull r; asm("mov.b64 %0, {%1, %1};" : "=l"(r) : "f"(x)); return r;
}
__device__ __forceinline__ ull pack2(float x, float y) {
    ull r; asm("mov.b64 %0, {%1, %2};" : "=l"(r) : "f"(x), "f"(y)); return r;
}
__device__ __forceinline__ float2 unpack2(ull v) {
    float2 r; asm("mov.b64 {%0, %1}, %2;" : "=f"(r.x), "=f"(r.y) : "l"(v)); return r;
}

// out = relu(f @ W1^T + b1) @ Wb^T + bb,  W1 = Wa@Wt, b1 = Wa@bt + ba.
// 4 lanes per point, each lane owns 4 output channels; all weights register-
// resident (permuted per-lane gather order); f and h exchanged via SHFL.IDX.
// Each layer accumulates on 4 independent f32x2 chains to hide FFMA latency.
__global__ void __launch_bounds__(128, 3)
dmasif_shfl_kernel(const float4* __restrict__ feat4,
                   const float* __restrict__ Wt,
                   const float* __restrict__ bt,
                   const float* __restrict__ Wa,
                   const float* __restrict__ ba,
                   const float* __restrict__ Wb,
                   const float* __restrict__ bb,
                   float4* __restrict__ out4,
                   int n)
{
    __shared__ float sW1[16][16];   // fused Wa@Wt, [out][in]
    __shared__ float sWb[16][16];   // Wb, [out][in]
    __shared__ float sb1[16];
    __shared__ float sbb[16];

    const int t = threadIdx.x;
    #pragma unroll
    for (int e = t; e < 256; e += 128) {
        const int c = e >> 4, j = e & 15;
        float acc = 0.f;
        #pragma unroll
        for (int k = 0; k < 16; k++)
            acc = fmaf(Wa[c * 16 + k], Wt[k * 16 + j], acc);
        sW1[c][j] = acc;
        sWb[c][j] = Wb[c * 16 + j];
    }
    if (t < 16) {
        float acc = ba[t];
        #pragma unroll
        for (int k = 0; k < 16; k++)
            acc = fmaf(Wa[t * 16 + k], bt[k], acc);
        sb1[t] = acc;
        sbb[t] = bb[t];
    }
    __syncthreads();

    const int lane = t & 31;
    const int q = lane & 3;

    // Register weights, permuted to this lane's gather order:
    // step i visits input channel j = ((q + i/4)&3)*4 + i%4.
    ull w1a[16], w1b[16], wba[16], wbb[16];
    #pragma unroll
    for (int i = 0; i < 16; i++) {
        const int j = (((q + (i >> 2)) & 3) << 2) | (i & 3);
        w1a[i] = pack2(sW1[4 * q + 0][j], sW1[4 * q + 1][j]);
        w1b[i] = pack2(sW1[4 * q + 2][j], sW1[4 * q + 3][j]);
        wba[i] = pack2(sWb[4 * q + 0][j], sWb[4 * q + 1][j]);
        wbb[i] = pack2(sWb[4 * q + 2][j], sWb[4 * q + 3][j]);
    }
    const ull b1p0 = pack2(sb1[4 * q + 0], sb1[4 * q + 1]);
    const ull b1p1 = pack2(sb1[4 * q + 2], sb1[4 * q + 3]);
    const ull bbp0 = pack2(sbb[4 * q + 0], sbb[4 * q + 1]);
    const ull bbp1 = pack2(sbb[4 * q + 2], sbb[4 * q + 3]);

    const unsigned FULL = 0xffffffffu;
    const int sb = lane & ~3;
    const int s1 = sb | ((q + 1) & 3);
    const int s2 = sb | ((q + 2) & 3);
    const int s3 = sb | ((q + 3) & 3);

    const int gwarp   = (blockIdx.x * blockDim.x + t) >> 5;
    const int nwarps  = (gridDim.x * blockDim.x) >> 5;
    const int ngroups = (n + 7) >> 3;      // 8 points per warp-iter
    if (gwarp >= ngroups) return;

    int grp = gwarp;
    float4 fcur;
    {
        const int p = grp * 8 + (lane >> 2);
        fcur = (p < n) ? feat4[grp * 32 + lane] : make_float4(0.f, 0.f, 0.f, 0.f);
    }

    for (;;) {
        const int nxt = grp + nwarps;
        const bool has_next = nxt < ngroups;
        float4 fnext = make_float4(0.f, 0.f, 0.f, 0.f);
        if (has_next) {
            const int pn = nxt * 8 + (lane >> 2);
            if (pn < n) fnext = feat4[nxt * 32 + lane];
        }

        // ---- layer 1: 4 independent chains (c0,c1 over j0..7; c2,c3 over j8..15)
        ull c0 = b1p0, c1 = b1p1, c2 = 0ull, c3 = 0ull;

        // shfl batch (independent of math; s-groups cover latency under own-group math)
        const float g1x = __shfl_sync(FULL, fcur.x, s1), g1y = __shfl_sync(FULL, fcur.y, s1);
        const float g1z = __shfl_sync(FULL, fcur.z, s1), g1w = __shfl_sync(FULL, fcur.w, s1);
        const float g2x = __shfl_sync(FULL, fcur.x, s2), g2y = __shfl_sync(FULL, fcur.y, s2);
        const float g2z = __shfl_sync(FULL, fcur.z, s2), g2w = __shfl_sync(FULL, fcur.w, s2);
        const float g3x = __shfl_sync(FULL, fcur.x, s3), g3y = __shfl_sync(FULL, fcur.y, s3);
        const float g3z = __shfl_sync(FULL, fcur.z, s3), g3w = __shfl_sync(FULL, fcur.w, s3);

        {   // own group -> c0,c1
            ull v;
            v = bcast2(fcur.x); c0 = ffma2(v, w1a[0], c0);  c1 = ffma2(v, w1b[0], c1);
            v = bcast2(fcur.y); c0 = ffma2(v, w1a[1], c0);  c1 = ffma2(v, w1b[1], c1);
            v = bcast2(fcur.z); c0 = ffma2(v, w1a[2], c0);  c1 = ffma2(v, w1b[2], c1);
            v = bcast2(fcur.w); c0 = ffma2(v, w1a[3], c0);  c1 = ffma2(v, w1b[3], c1);
            // s2 group -> c2,c3 (interleaved chain pair)
            v = bcast2(g2x);    c2 = ffma2(v, w1a[8], c2);  c3 = ffma2(v, w1b[8], c3);
            v = bcast2(g2y);    c2 = ffma2(v, w1a[9], c2);  c3 = ffma2(v, w1b[9], c3);
            v = bcast2(g2z);    c2 = ffma2(v, w1a[10], c2); c3 = ffma2(v, w1b[10], c3);
            v = bcast2(g2w);    c2 = ffma2(v, w1a[11], c2); c3 = ffma2(v, w1b[11], c3);
            // s1 group -> c0,c1
            v = bcast2(g1x);    c0 = ffma2(v, w1a[4], c0);  c1 = ffma2(v, w1b[4], c1);
            v = bcast2(g1y);    c0 = ffma2(v, w1a[5], c0);  c1 = ffma2(v, w1b[5], c1);
            v = bcast2(g1z);    c0 = ffma2(v, w1a[6], c0);  c1 = ffma2(v, w1b[6], c1);
            v = bcast2(g1w);    c0 = ffma2(v, w1a[7], c0);  c1 = ffma2(v, w1b[7], c1);
            // s3 group -> c2,c3
            v = bcast2(g3x);    c2 = ffma2(v, w1a[12], c2); c3 = ffma2(v, w1b[12], c3);
            v = bcast2(g3y);    c2 = ffma2(v, w1a[13], c2); c3 = ffma2(v, w1b[13], c3);
            v = bcast2(g3z);    c2 = ffma2(v, w1a[14], c2); c3 = ffma2(v, w1b[14], c3);
            v = bcast2(g3w);    c2 = ffma2(v, w1a[15], c2); c3 = ffma2(v, w1b[15], c3);
        }
        const ull a0 = add2(c0, c2);
        const ull a1 = add2(c1, c3);

        // ---- ReLU: this lane owns h channels 4q..4q+3
        const float2 u0 = unpack2(a0), u1 = unpack2(a1);
        const float h0 = fmaxf(u0.x, 0.f), h1 = fmaxf(u0.y, 0.f);
        const float h2 = fmaxf(u1.x, 0.f), h3 = fmaxf(u1.y, 0.f);

        // ---- layer 2: same 4-chain structure
        ull d0 = bbp0, d1 = bbp1, d2 = 0ull, d3 = 0ull;

        const float k1x = __shfl_sync(FULL, h0, s1), k1y = __shfl_sync(FULL, h1, s1);
        const float k1z = __shfl_sync(FULL, h2, s1), k1w = __shfl_sync(FULL, h3, s1);
        const float k2x = __shfl_sync(FULL, h0, s2), k2y = __shfl_sync(FULL, h1, s2);
        const float k2z = __shfl_sync(FULL, h2, s2), k2w = __shfl_sync(FULL, h3, s2);
        const float k3x = __shfl_sync(FULL, h0, s3), k3y = __shfl_sync(FULL, h1, s3);
        const float k3z = __shfl_sync(FULL, h2, s3), k3w = __shfl_sync(FULL, h3, s3);

        {
            ull v;
            v = bcast2(h0);  d0 = ffma2(v, wba[0], d0);  d1 = ffma2(v, wbb[0], d1);
            v = bcast2(h1);  d0 = ffma2(v, wba[1], d0);  d1 = ffma2(v, wbb[1], d1);
            v = bcast2(h2);  d0 = ffma2(v, wba[2], d0);  d1 = ffma2(v, wbb[2], d1);
            v = bcast2(h3);  d0 = ffma2(v, wba[3], d0);  d1 = ffma2(v, wbb[3], d1);
            v = bcast2(k2x); d2 = ffma2(v, wba[8], d2);  d3 = ffma2(v, wbb[8], d3);
            v = bcast2(k2y); d2 = ffma2(v, wba[9], d2);  d3 = ffma2(v, wbb[9], d3);
            v = bcast2(k2z); d2 = ffma2(v, wba[10], d2); d3 = ffma2(v, wbb[10], d3);
            v = bcast2(k2w); d2 = ffma2(v, wba[11], d2); d3 = ffma2(v, wbb[11], d3);
            v = bcast2(k1x); d0 = ffma2(v, wba[4], d0);  d1 = ffma2(v, wbb[4], d1);
            v = bcast2(k1y); d0 = ffma2(v, wba[5], d0);  d1 = ffma2(v, wbb[5], d1);
            v = bcast2(k1z); d0 = ffma2(v, wba[6], d0);  d1 = ffma2(v, wbb[6], d1);
            v = bcast2(k1w); d0 = ffma2(v, wba[7], d0);  d1 = ffma2(v, wbb[7], d1);
            v = bcast2(k3x); d2 = ffma2(v, wba[12], d2); d3 = ffma2(v, wbb[12], d3);
            v = bcast2(k3y); d2 = ffma2(v, wba[13], d2); d3 = ffma2(v, wbb[13], d3);
            v = bcast2(k3z); d2 = ffma2(v, wba[14], d2); d3 = ffma2(v, wbb[14], d3);
            v = bcast2(k3w); d2 = ffma2(v, wba[15], d2); d3 = ffma2(v, wbb[15], d3);
        }
        const ull r0 = add2(d0, d2);
        const ull r1 = add2(d1, d3);

        {
            const int p = grp * 8 + (lane >> 2);
            if (p < n) {
                const float2 o0 = unpack2(r0), o1 = unpack2(r1);
                out4[grp * 32 + lane] = make_float4(o0.x, o0.y, o1.x, o1.y);
            }
        }

        if (!has_next) break;
        grp = nxt;
        fcur = fnext;
    }
}

extern "C" void kernel_launch(void* const* d_in, const int* in_sizes, int n_in,
                              void* d_out, int out_size)
{
    // metadata order: features, points, nuv, Wt, bt, Wa, ba, Wb, bb, ranges
    const float4* feat = (const float4*)d_in[0];
    const float*  Wt   = (const float*)d_in[3];
    const float*  bt   = (const float*)d_in[4];
    const float*  Wa   = (const float*)d_in[5];
    const float*  ba   = (const float*)d_in[6];
    const float*  Wb   = (const float*)d_in[7];
    const float*  bb   = (const float*)d_in[8];
    float4* out = (float4*)d_out;

    const int n = in_sizes[0] / 16;   // number of points
    const int ngroups = (n + 7) / 8;
    int blocks = 148 * 3;             // exactly resident (3 CTAs/SM at <=170 regs)
    const int maxBlocks = (ngroups * 32 + 127) / 128;
    if (blocks > maxBlocks) blocks = maxBlocks;
    if (blocks < 1) blocks = 1;
    dmasif_shfl_kernel<<<blocks, 128>>>(feat, Wt, bt, Wa, ba, Wb, bb, out, n);
}